// round 16
// baseline (speedup 1.0000x reference)
#include <cuda_runtime.h>
#include <cuda_fp16.h>
#include <cstdint>
#include <math.h>

// Fixed shapes (registry): N=65536, M=2048, d=256, K=512
#define NN 65536
#define MM 2048
#define DD 256
#define KK 512
#define LN_EPS 1e-5f

// ---------------- static scratch (no allocations allowed) ----------------
__device__ __align__(256) float  g_S   [(size_t)NN * MM];  // 512MB scores fp32
__device__ __align__(256) float  g_rowmax[NN];             // row maxima of S
__device__ __align__(256) __half g_Ahi [(size_t)NN * KK];
__device__ __align__(256) __half g_Alo [(size_t)NN * KK];
__device__ __align__(256) __half g_Hrhi[(size_t)NN * DD];
__device__ __align__(256) __half g_Hrlo[(size_t)NN * DD];
__device__ __align__(256) __half g_Hdhi[(size_t)MM * DD];
__device__ __align__(256) __half g_Hdlo[(size_t)MM * DD];
__device__ __align__(256) __half g_Vhi [(size_t)KK * DD];
__device__ __align__(256) __half g_Vlo [(size_t)KK * DD];
__device__ __align__(256) __half g_DpThi[(size_t)MM * KK];
__device__ __align__(256) __half g_DpTlo[(size_t)MM * KK];
__device__ __align__(256) __half g_HdThi[(size_t)DD * MM];
__device__ __align__(256) __half g_Uthi [(size_t)KK * DD];
__device__ __align__(256) __half g_Utlo [(size_t)KK * DD];

// ---------------- helpers ----------------
__device__ __forceinline__ uint32_t smem_u32(const void* p) {
    uint32_t a;
    asm("{ .reg .u64 t; cvta.to.shared.u64 t, %1; cvt.u32.u64 %0, t; }" : "=r"(a) : "l"(p));
    return a;
}
__device__ __forceinline__ void cp16(uint32_t dst, const void* src) {
    asm volatile("cp.async.cg.shared.global [%0], [%1], 16;" :: "r"(dst), "l"(src));
}
#define CP_COMMIT()  asm volatile("cp.async.commit_group;" ::: "memory")
#define CP_WAIT0()   asm volatile("cp.async.wait_group 0;"  ::: "memory")
#define CP_WAIT1()   asm volatile("cp.async.wait_group 1;"  ::: "memory")

#define LDSM4(r, addr) \
    asm volatile("ldmatrix.sync.aligned.m8n8.x4.shared.b16 {%0,%1,%2,%3}, [%4];" \
        : "=r"((r)[0]), "=r"((r)[1]), "=r"((r)[2]), "=r"((r)[3]) : "r"(addr))

#define MMA16816(c, a, b0, b1) \
    asm volatile("mma.sync.aligned.m16n8k16.row.col.f32.f16.f16.f32 " \
        "{%0,%1,%2,%3}, {%4,%5,%6,%7}, {%8,%9}, {%0,%1,%2,%3};" \
        : "+f"((c)[0]), "+f"((c)[1]), "+f"((c)[2]), "+f"((c)[3]) \
        : "r"((a)[0]), "r"((a)[1]), "r"((a)[2]), "r"((a)[3]), "r"(b0), "r"(b1))

__device__ __forceinline__ void split2h(float x, __half& h, __half& l) {
    h = __float2half(x);
    l = __float2half(x - __half2float(h));
}
__device__ __forceinline__ uint32_t pack2h(float a, float b) {
    __half2 h = __floats2half2_rn(a, b);
    return *(uint32_t*)&h;
}
__device__ __forceinline__ void atomicMaxFloat(float* addr, float val) {
    int* ia = (int*)addr;
    int old = *ia;
    while (__int_as_float(old) < val) {
        int assumed = old;
        old = atomicCAS(ia, assumed, __float_as_int(val));
        if (old == assumed) break;
    }
}

// ============ stage-4 HMMA GEMM: S[N,M] = A[N,512] @ DpT[M,512]^T, fused rowmax ============
// 128x256 tile, BK=32, 3-stage ring (48KB/stage), 512 threads, 1 CTA/SM, fp16 x3 split.
// Warp map: wr = wid>>2 (0..3, 32-row), wc = wid&3 (0..3, 64-col). Per-warp fragment
// structure identical to the proven 128x128 kernel.
__global__ void __launch_bounds__(512, 1)
gemm_s(const __half* __restrict__ Ahi, const __half* __restrict__ Alo,
       const __half* __restrict__ Bhi, const __half* __restrict__ Blo,
       float* __restrict__ C, int Ktot, int Ncols, float* __restrict__ rowmax)
{
    extern __shared__ char smem[];
    const int tid  = threadIdx.x;
    const int wid  = tid >> 5, lane = tid & 31;
    const int row0 = blockIdx.y * 128;
    const int col0 = blockIdx.x * 256;
    const int nch  = Ktot >> 5;

    const uint32_t sb = smem_u32(smem);   // 3 stages x (A 16KB + B 32KB)

    const int wr = wid >> 2;
    const int wc = wid & 3;
    const int lm = lane >> 3;
    const int lr = lane & 7;

    float acc[2][8][4];
    #pragma unroll
    for (int i = 0; i < 2; i++)
        #pragma unroll
        for (int j = 0; j < 8; j++)
            #pragma unroll
            for (int k = 0; k < 4; k++) acc[i][j][k] = 0.f;

    auto load_chunk = [&](int ch, int stage) {
        const int kc0 = ch << 5;
        const uint32_t Ab = sb + (uint32_t)stage * 49152u;
        const uint32_t Bb = Ab + 16384u;
        #pragma unroll
        for (int g = tid; g < 1024; g += 512) {       // A: 128 rows x 8 segs
            int r = g >> 3, s = g & 7;
            int split = s >> 2, seg = s & 3;
            const __half* src = (split ? Alo : Ahi) + (size_t)(row0 + r) * Ktot + kc0 + seg * 8;
            uint32_t off = (uint32_t)(r * 128 + split * 64 + seg * 16);
            cp16(Ab + (off ^ ((off >> 3) & 0x70)), src);
        }
        #pragma unroll
        for (int g = tid; g < 2048; g += 512) {       // B: 256 rows x 8 segs
            int r = g >> 3, s = g & 7;
            int split = s >> 2, seg = s & 3;
            const __half* src = (split ? Blo : Bhi) + (size_t)(col0 + r) * Ktot + kc0 + seg * 8;
            uint32_t off = (uint32_t)(r * 128 + split * 64 + seg * 16);
            cp16(Bb + (off ^ ((off >> 3) & 0x70)), src);
        }
        CP_COMMIT();
    };

    auto compute = [&](int stage) {
        const uint32_t Ab = sb + (uint32_t)stage * 49152u;
        const uint32_t Bb = Ab + 16384u;
        #pragma unroll
        for (int ks = 0; ks < 2; ks++) {
            uint32_t ah[2][4], al[2][4];
            #pragma unroll
            for (int mt = 0; mt < 2; mt++) {
                int r = wr * 32 + mt * 16 + (lm & 1) * 8 + lr;
                int ch = ks * 32 + (lm >> 1) * 16;
                uint32_t rowa = Ab + (uint32_t)(r * 128);
                LDSM4(ah[mt], rowa + (uint32_t)( ch       ^ ((r & 7) << 4)));
                LDSM4(al[mt], rowa + (uint32_t)((ch + 64) ^ ((r & 7) << 4)));
            }
            uint32_t b[4][4];
            #pragma unroll
            for (int nt2 = 0; nt2 < 4; nt2++) {
                int r = wc * 64 + nt2 * 16 + (lm >> 1) * 8 + lr;
                int cb = ks * 32 + (lm & 1) * 16;
                LDSM4(b[nt2], Bb + (uint32_t)(r * 128) + (uint32_t)(cb ^ ((r & 7) << 4)));
            }
            #pragma unroll
            for (int mt = 0; mt < 2; mt++)
                #pragma unroll
                for (int nt = 0; nt < 8; nt++)
                    MMA16816(acc[mt][nt], ah[mt],
                             b[nt >> 1][(nt & 1) * 2], b[nt >> 1][(nt & 1) * 2 + 1]);
            #pragma unroll
            for (int mt = 0; mt < 2; mt++)
                #pragma unroll
                for (int nt = 0; nt < 8; nt++)
                    MMA16816(acc[mt][nt], al[mt],
                             b[nt >> 1][(nt & 1) * 2], b[nt >> 1][(nt & 1) * 2 + 1]);
            #pragma unroll
            for (int nt2 = 0; nt2 < 4; nt2++) {
                int r = wc * 64 + nt2 * 16 + (lm >> 1) * 8 + lr;
                int cb = 64 + ks * 32 + (lm & 1) * 16;
                LDSM4(b[nt2], Bb + (uint32_t)(r * 128) + (uint32_t)(cb ^ ((r & 7) << 4)));
            }
            #pragma unroll
            for (int mt = 0; mt < 2; mt++)
                #pragma unroll
                for (int nt = 0; nt < 8; nt++)
                    MMA16816(acc[mt][nt], ah[mt],
                             b[nt >> 1][(nt & 1) * 2], b[nt >> 1][(nt & 1) * 2 + 1]);
        }
    };

    load_chunk(0, 0);
    load_chunk(1, 1);
    for (int i = 0; i < nch; i++) {
        if (i + 1 < nch) CP_WAIT1(); else CP_WAIT0();
        __syncthreads();
        if (i + 2 < nch) {
            int st = i + 2; st -= (st / 3) * 3;
            load_chunk(i + 2, st);
        }
        int cs = i; cs -= (cs / 3) * 3;
        compute(cs);
    }

    #pragma unroll
    for (int mt = 0; mt < 2; mt++) {
        float rmax0 = -INFINITY, rmax1 = -INFINITY;
        #pragma unroll
        for (int nt = 0; nt < 8; nt++) {
            int r = row0 + wr * 32 + mt * 16 + (lane >> 2);
            int c = col0 + wc * 64 + nt * 8 + (lane & 3) * 2;
            float2 v0 = make_float2(acc[mt][nt][0], acc[mt][nt][1]);
            float2 v1 = make_float2(acc[mt][nt][2], acc[mt][nt][3]);
            rmax0 = fmaxf(rmax0, fmaxf(v0.x, v0.y));
            rmax1 = fmaxf(rmax1, fmaxf(v1.x, v1.y));
            *(float2*)&C[(size_t)r * Ncols + c]       = v0;
            *(float2*)&C[(size_t)(r + 8) * Ncols + c] = v1;
        }
        rmax0 = fmaxf(rmax0, __shfl_xor_sync(0xffffffffu, rmax0, 1));
        rmax0 = fmaxf(rmax0, __shfl_xor_sync(0xffffffffu, rmax0, 2));
        rmax1 = fmaxf(rmax1, __shfl_xor_sync(0xffffffffu, rmax1, 1));
        rmax1 = fmaxf(rmax1, __shfl_xor_sync(0xffffffffu, rmax1, 2));
        if ((lane & 3) == 0) {
            int r = row0 + wr * 32 + mt * 16 + (lane >> 2);
            atomicMaxFloat(&rowmax[r],     rmax0);
            atomicMaxFloat(&rowmax[r + 8], rmax1);
        }
    }
}

// ============ fused GEMM + tanh + LayerNorm (+ optional *q) + fp16 split ============
// Tile 64 rows x 512 out-cols (FULL LN axis), inner dim 256, BK=32 (8 chunks), 512 threads.
// Two jobs in one grid: blocks [0, nblk1) = drug, [nblk1, ...) = rna (QMUL).
__global__ void __launch_bounds__(512, 1)
gemm_ln(const __half* __restrict__ A1hi, const __half* __restrict__ A1lo,
        const __half* __restrict__ B1hi, const __half* __restrict__ B1lo,
        const float* __restrict__ g1, const float* __restrict__ b1,
        __half* __restrict__ O1hi, __half* __restrict__ O1lo, int nblk1,
        const __half* __restrict__ A2hi, const __half* __restrict__ A2lo,
        const __half* __restrict__ B2hi, const __half* __restrict__ B2lo,
        const float* __restrict__ g2, const float* __restrict__ b2,
        const float* __restrict__ q2,
        __half* __restrict__ O2hi, __half* __restrict__ O2lo)
{
    extern __shared__ char smem[];
    float* lnsum  = (float*)(smem + 3 * 73728);
    float* lnsum2 = lnsum + 64;
    const uint32_t sb = smem_u32(smem);

    const bool job2 = (int)blockIdx.x >= nblk1;
    const __half* Ahi = job2 ? A2hi : A1hi;
    const __half* Alo = job2 ? A2lo : A1lo;
    const __half* Bhi = job2 ? B2hi : B1hi;
    const __half* Blo = job2 ? B2lo : B1lo;
    const float*  gp  = job2 ? g2 : g1;
    const float*  bp  = job2 ? b2 : b1;
    __half* Ohi = job2 ? O2hi : O1hi;
    __half* Olo = job2 ? O2lo : O1lo;
    const int row0 = (job2 ? ((int)blockIdx.x - nblk1) : (int)blockIdx.x) * 64;

    const int tid  = threadIdx.x;
    const int wid  = tid >> 5, lane = tid & 31;
    const int wr = wid >> 2, wc = wid & 3;
    const int lm = lane >> 3, lr = lane & 7;

    if (tid < 64) { lnsum[tid] = 0.f; lnsum2[tid] = 0.f; }

    float acc[16][4];
    #pragma unroll
    for (int i = 0; i < 16; i++)
        #pragma unroll
        for (int j = 0; j < 4; j++) acc[i][j] = 0.f;

    auto load_chunk = [&](int ch, int stage) {
        const int kc0 = ch << 5;
        const uint32_t Ab = sb + (uint32_t)stage * 73728u;
        const uint32_t Bb = Ab + 8192u;
        {
            int r = tid >> 3, s = tid & 7;
            int split = s >> 2, seg = s & 3;
            const __half* src = (split ? Alo : Ahi) + (size_t)(row0 + r) * 256 + kc0 + seg * 8;
            uint32_t off = (uint32_t)(r * 128 + split * 64 + seg * 16);
            cp16(Ab + (off ^ ((off >> 3) & 0x70)), src);
        }
        #pragma unroll
        for (int g = tid; g < 4096; g += 512) {
            int r = g >> 3, s = g & 7;
            int split = s >> 2, seg = s & 3;
            const __half* src = (split ? Blo : Bhi) + (size_t)r * 256 + kc0 + seg * 8;
            uint32_t off = (uint32_t)(r * 128 + split * 64 + seg * 16);
            cp16(Bb + (off ^ ((off >> 3) & 0x70)), src);
        }
        CP_COMMIT();
    };

    auto compute = [&](int stage) {
        const uint32_t Ab = sb + (uint32_t)stage * 73728u;
        const uint32_t Bb = Ab + 8192u;
        #pragma unroll
        for (int ks = 0; ks < 2; ks++) {
            uint32_t ah[4], al[4];
            {
                int r = wr * 16 + (lm & 1) * 8 + lr;
                int ch = ks * 32 + (lm >> 1) * 16;
                uint32_t rowa = Ab + (uint32_t)(r * 128);
                LDSM4(ah, rowa + (uint32_t)( ch       ^ ((r & 7) << 4)));
                LDSM4(al, rowa + (uint32_t)((ch + 64) ^ ((r & 7) << 4)));
            }
            #pragma unroll
            for (int half = 0; half < 2; half++) {
                uint32_t b[4][4];
                #pragma unroll
                for (int nt2 = 0; nt2 < 4; nt2++) {
                    int gi = half * 4 + nt2;
                    int r  = wc * 128 + gi * 16 + (lm >> 1) * 8 + lr;
                    int cb = ks * 32 + (lm & 1) * 16;
                    LDSM4(b[nt2], Bb + (uint32_t)(r * 128) + (uint32_t)(cb ^ ((r & 7) << 4)));
                }
                #pragma unroll
                for (int nt2 = 0; nt2 < 4; nt2++) {
                    int ai = (half * 4 + nt2) * 2;
                    MMA16816(acc[ai],     ah, b[nt2][0], b[nt2][1]);
                    MMA16816(acc[ai + 1], ah, b[nt2][2], b[nt2][3]);
                    MMA16816(acc[ai],     al, b[nt2][0], b[nt2][1]);
                    MMA16816(acc[ai + 1], al, b[nt2][2], b[nt2][3]);
                }
                #pragma unroll
                for (int nt2 = 0; nt2 < 4; nt2++) {
                    int gi = half * 4 + nt2;
                    int r  = wc * 128 + gi * 16 + (lm >> 1) * 8 + lr;
                    int cb = 64 + ks * 32 + (lm & 1) * 16;
                    LDSM4(b[nt2], Bb + (uint32_t)(r * 128) + (uint32_t)(cb ^ ((r & 7) << 4)));
                }
                #pragma unroll
                for (int nt2 = 0; nt2 < 4; nt2++) {
                    int ai = (half * 4 + nt2) * 2;
                    MMA16816(acc[ai],     ah, b[nt2][0], b[nt2][1]);
                    MMA16816(acc[ai + 1], ah, b[nt2][2], b[nt2][3]);
                }
            }
        }
    };

    load_chunk(0, 0);
    load_chunk(1, 1);
    for (int i = 0; i < 8; i++) {
        if (i + 1 < 8) CP_WAIT1(); else CP_WAIT0();
        __syncthreads();
        if (i + 2 < 8) {
            int st = i + 2; st -= (st / 3) * 3;
            load_chunk(i + 2, st);
        }
        int cs = i; cs -= (cs / 3) * 3;
        compute(cs);
    }

    // ---- epilogue: tanh + per-row LN over 512 cols ----
    const int r0l = wr * 16 + (lane >> 2);
    float s0 = 0.f, s20 = 0.f, s1 = 0.f, s21 = 0.f;
    #pragma unroll
    for (int ai = 0; ai < 16; ai++) {
        float v0 = tanhf(acc[ai][0]), v1 = tanhf(acc[ai][1]);
        float v2 = tanhf(acc[ai][2]), v3 = tanhf(acc[ai][3]);
        acc[ai][0] = v0; acc[ai][1] = v1; acc[ai][2] = v2; acc[ai][3] = v3;
        s0 += v0 + v1; s20 += v0 * v0 + v1 * v1;
        s1 += v2 + v3; s21 += v2 * v2 + v3 * v3;
    }
    s0  += __shfl_xor_sync(0xffffffffu, s0, 1);  s0  += __shfl_xor_sync(0xffffffffu, s0, 2);
    s20 += __shfl_xor_sync(0xffffffffu, s20, 1); s20 += __shfl_xor_sync(0xffffffffu, s20, 2);
    s1  += __shfl_xor_sync(0xffffffffu, s1, 1);  s1  += __shfl_xor_sync(0xffffffffu, s1, 2);
    s21 += __shfl_xor_sync(0xffffffffu, s21, 1); s21 += __shfl_xor_sync(0xffffffffu, s21, 2);
    if ((lane & 3) == 0) {
        atomicAdd(&lnsum [r0l],     s0);
        atomicAdd(&lnsum2[r0l],     s20);
        atomicAdd(&lnsum [r0l + 8], s1);
        atomicAdd(&lnsum2[r0l + 8], s21);
    }
    __syncthreads();

    const float mu0   = lnsum[r0l] * (1.f / 512.f);
    const float rstd0 = rsqrtf(lnsum2[r0l] * (1.f / 512.f) - mu0 * mu0 + LN_EPS);
    const float mu1   = lnsum[r0l + 8] * (1.f / 512.f);
    const float rstd1 = rsqrtf(lnsum2[r0l + 8] * (1.f / 512.f) - mu1 * mu1 + LN_EPS);
    const int grow = row0 + r0l;

    #pragma unroll
    for (int ai = 0; ai < 16; ai++) {
        int c = wc * 128 + (ai >> 1) * 16 + (ai & 1) * 8 + (lane & 3) * 2;
        float2 gv = *(const float2*)(gp + c);
        float2 bv = *(const float2*)(bp + c);
        float y0 = (acc[ai][0] - mu0) * rstd0 * gv.x + bv.x;
        float y1 = (acc[ai][1] - mu0) * rstd0 * gv.y + bv.y;
        float y2 = (acc[ai][2] - mu1) * rstd1 * gv.x + bv.x;
        float y3 = (acc[ai][3] - mu1) * rstd1 * gv.y + bv.y;
        if (job2) {
            float2 qv = *(const float2*)(q2 + c);
            y0 *= qv.x; y1 *= qv.y; y2 *= qv.x; y3 *= qv.y;
        }
        __half h0, l0, h1, l1, h2, l2, h3, l3;
        split2h(y0, h0, l0); split2h(y1, h1, l1);
        split2h(y2, h2, l2); split2h(y3, h3, l3);
        *(__half2*)&Ohi[(size_t)grow * 512 + c]       = __halves2half2(h0, h1);
        *(__half2*)&Olo[(size_t)grow * 512 + c]       = __halves2half2(l0, l1);
        *(__half2*)&Ohi[(size_t)(grow + 8) * 512 + c] = __halves2half2(h2, h3);
        *(__half2*)&Olo[(size_t)(grow + 8) * 512 + c] = __halves2half2(l2, l3);
    }
}

// ============ fused softmax + O = softmax(S) @ Hd ============
__global__ void __launch_bounds__(512, 1)
softmax_pv(const float* __restrict__ S, const __half* __restrict__ HdThi,
           const float* __restrict__ rowmax, float* __restrict__ O, int M, int d)
{
    extern __shared__ char smem[];
    float* smax = (float*)(smem + 65536);
    float* ssum = smax + 128;
    const uint32_t sb = smem_u32(smem);
    const int tid  = threadIdx.x;
    const int wid  = tid >> 5, lane = tid & 31;
    const int wr   = wid >> 1, wc = wid & 1;
    const int lm   = lane >> 3, lr = lane & 7;
    const int row0 = blockIdx.x * 128;

    if (tid < 128) {
        smax[tid] = rowmax[row0 + tid];
        ssum[tid] = 0.f;
    }
    __syncthreads();

    const int nch  = M >> 5;
    const int r0l  = wr * 16 + (lane >> 2);
    const float mx0 = smax[r0l];
    const float mx1 = smax[r0l + 8];
    const float* Sr0 = S + (size_t)(row0 + r0l) * M + (lane & 3) * 2;
    const float* Sr1 = S + (size_t)(row0 + r0l + 8) * M + (lane & 3) * 2;

    float acc[16][4];
    #pragma unroll
    for (int i = 0; i < 16; i++)
        #pragma unroll
        for (int j = 0; j < 4; j++) acc[i][j] = 0.f;
    float psum0 = 0.f, psum1 = 0.f;

    auto loadB = [&](int ch, int buf) {
        const int m0 = ch << 5;
        const uint32_t Bb = sb + (uint32_t)buf * 32768u;
        #pragma unroll
        for (int g = tid; g < 1024; g += 512) {
            int r = g >> 2, seg = g & 3;
            const __half* src = HdThi + (size_t)r * M + m0 + seg * 8;
            uint32_t off = (uint32_t)(r * 128 + seg * 16);
            cp16(Bb + (off ^ ((off >> 3) & 0x70)), src);
        }
        CP_COMMIT();
    };
    auto loadS = [&](int ch, float2* sp) {
        const int c0 = ch << 5;
        sp[0] = *(const float2*)(Sr0 + c0);
        sp[1] = *(const float2*)(Sr0 + c0 + 8);
        sp[2] = *(const float2*)(Sr0 + c0 + 16);
        sp[3] = *(const float2*)(Sr0 + c0 + 24);
        sp[4] = *(const float2*)(Sr1 + c0);
        sp[5] = *(const float2*)(Sr1 + c0 + 8);
        sp[6] = *(const float2*)(Sr1 + c0 + 16);
        sp[7] = *(const float2*)(Sr1 + c0 + 24);
    };

    float2 spc[8];
    loadB(0, 0);
    loadS(0, spc);

    for (int c = 0; c < nch; c++) {
        float2 spn[8];
        if (c + 1 < nch) {
            loadB(c + 1, (c + 1) & 1);
            loadS(c + 1, spn);
            CP_WAIT1();
        } else {
            CP_WAIT0();
        }
        __syncthreads();

        const uint32_t Bb = sb + (uint32_t)(c & 1) * 32768u;
        #pragma unroll
        for (int ks = 0; ks < 2; ks++) {
            float e00 = __expf(spc[2*ks    ].x - mx0), e01 = __expf(spc[2*ks    ].y - mx0);
            float e02 = __expf(spc[2*ks + 1].x - mx0), e03 = __expf(spc[2*ks + 1].y - mx0);
            float e10 = __expf(spc[4 + 2*ks    ].x - mx1), e11 = __expf(spc[4 + 2*ks    ].y - mx1);
            float e12 = __expf(spc[4 + 2*ks + 1].x - mx1), e13 = __expf(spc[4 + 2*ks + 1].y - mx1);
            psum0 += e00 + e01 + e02 + e03;
            psum1 += e10 + e11 + e12 + e13;
            uint32_t ah[4];
            ah[0] = pack2h(e00, e01); ah[1] = pack2h(e10, e11);
            ah[2] = pack2h(e02, e03); ah[3] = pack2h(e12, e13);
            #pragma unroll
            for (int nt2 = 0; nt2 < 8; nt2++) {
                int r  = wc * 128 + nt2 * 16 + (lm >> 1) * 8 + lr;
                int cb = ks * 32 + (lm & 1) * 16;
                uint32_t b[4];
                LDSM4(b, Bb + (uint32_t)(r * 128) + (uint32_t)(cb ^ ((r & 7) << 4)));
                MMA16816(acc[nt2 * 2    ], ah, b[0], b[1]);
                MMA16816(acc[nt2 * 2 + 1], ah, b[2], b[3]);
            }
        }
        #pragma unroll
        for (int i = 0; i < 8; i++) spc[i] = spn[i];
        __syncthreads();
    }

    psum0 += __shfl_xor_sync(0xffffffffu, psum0, 1);
    psum0 += __shfl_xor_sync(0xffffffffu, psum0, 2);
    psum1 += __shfl_xor_sync(0xffffffffu, psum1, 1);
    psum1 += __shfl_xor_sync(0xffffffffu, psum1, 2);
    if ((lane & 3) == 0 && wc == 0) {
        atomicAdd(&ssum[r0l],     psum0);
        atomicAdd(&ssum[r0l + 8], psum1);
    }
    __syncthreads();
    const float inv0 = 1.f / ssum[r0l];
    const float inv1 = 1.f / ssum[r0l + 8];

    #pragma unroll
    for (int nt2 = 0; nt2 < 8; nt2++) {
        #pragma unroll
        for (int j = 0; j < 2; j++) {
            int col = wc * 128 + nt2 * 16 + j * 8 + (lane & 3) * 2;
            float* a4 = acc[nt2 * 2 + j];
            *(float2*)&O[(size_t)(row0 + r0l)     * d + col] =
                make_float2(a4[0] * inv0, a4[1] * inv0);
            *(float2*)&O[(size_t)(row0 + r0l + 8) * d + col] =
                make_float2(a4[2] * inv1, a4[3] * inv1);
        }
    }
}

// ---------------- prep kernels ----------------
__global__ void split_kernel(const float* __restrict__ in,
                             __half* __restrict__ hi, __half* __restrict__ lo, size_t n)
{
    for (size_t i = (size_t)blockIdx.x * blockDim.x + threadIdx.x; i < n;
         i += (size_t)gridDim.x * blockDim.x) {
        __half h, l; split2h(in[i], h, l);
        hi[i] = h; lo[i] = l;
    }
}

__global__ void prep_small(const float* __restrict__ Hd, const float* __restrict__ V,
                           const float* __restrict__ U,
                           __half* __restrict__ Hdhi, __half* __restrict__ Hdlo,
                           __half* __restrict__ HdThi,
                           __half* __restrict__ Vhi, __half* __restrict__ Vlo,
                           __half* __restrict__ Uthi, __half* __restrict__ Utlo,
                           float* __restrict__ rm)
{
    const int i0 = blockIdx.x * blockDim.x + threadIdx.x;
    const int stride = gridDim.x * blockDim.x;
    for (int t = i0; t < MM * DD; t += stride) {
        __half h, l; split2h(Hd[t], h, l);
        Hdhi[t] = h; Hdlo[t] = l;
        int m = t >> 8, dd = t & 255;
        HdThi[(size_t)dd * MM + m] = h;
    }
    for (int t = i0; t < KK * DD; t += stride) {
        __half h, l; split2h(V[t], h, l);
        Vhi[t] = h; Vlo[t] = l;
    }
    for (int t = i0; t < DD * KK; t += stride) {
        int r = t >> 9, c = t & 511;
        __half h, l; split2h(U[t], h, l);
        Uthi[(size_t)c * DD + r] = h;
        Utlo[(size_t)c * DD + r] = l;
    }
    for (int t = i0; t < NN; t += stride) rm[t] = -INFINITY;
}

// ---------------- launch ----------------
extern "C" void kernel_launch(void* const* d_in, const int* in_sizes, int n_in,
                              void* d_out, int out_size)
{
    const float* H_rna  = (const float*)d_in[0];
    const float* H_drug = (const float*)d_in[1];
    const float* U      = (const float*)d_in[2];
    const float* V      = (const float*)d_in[3];
    const float* q      = (const float*)d_in[4];
    const float* g_rna  = (const float*)d_in[5];
    const float* b_rna  = (const float*)d_in[6];
    const float* g_drug = (const float*)d_in[7];
    const float* b_drug = (const float*)d_in[8];

    const int K = in_sizes[4];             // 512
    const int d = in_sizes[2] / K;         // 256
    const int N = in_sizes[0] / d;         // 65536
    const int M = in_sizes[1] / d;         // 2048

    float *pS, *pRM;
    __half *pAhi, *pAlo, *pHrhi, *pHrlo, *pHdhi, *pHdlo, *pVhi, *pVlo;
    __half *pDpThi, *pDpTlo, *pHdThi, *pUthi, *pUtlo;
    cudaGetSymbolAddress((void**)&pS,     g_S);
    cudaGetSymbolAddress((void**)&pRM,    g_rowmax);
    cudaGetSymbolAddress((void**)&pAhi,   g_Ahi);
    cudaGetSymbolAddress((void**)&pAlo,   g_Alo);
    cudaGetSymbolAddress((void**)&pHrhi,  g_Hrhi);
    cudaGetSymbolAddress((void**)&pHrlo,  g_Hrlo);
    cudaGetSymbolAddress((void**)&pHdhi,  g_Hdhi);
    cudaGetSymbolAddress((void**)&pHdlo,  g_Hdlo);
    cudaGetSymbolAddress((void**)&pVhi,   g_Vhi);
    cudaGetSymbolAddress((void**)&pVlo,   g_Vlo);
    cudaGetSymbolAddress((void**)&pDpThi, g_DpThi);
    cudaGetSymbolAddress((void**)&pDpTlo, g_DpTlo);
    cudaGetSymbolAddress((void**)&pHdThi, g_HdThi);
    cudaGetSymbolAddress((void**)&pUthi,  g_Uthi);
    cudaGetSymbolAddress((void**)&pUtlo,  g_Utlo);

    const int SMEMS4 = 3 * 49152;                // gemm_s: 3 x 48KB = 144KB
    cudaFuncSetAttribute(gemm_s, cudaFuncAttributeMaxDynamicSharedMemorySize, SMEMS4);
    const int SMEMLN = 3 * 73728 + 512;          // gemm_ln: 3 x 72KB + lnsum
    cudaFuncSetAttribute(gemm_ln, cudaFuncAttributeMaxDynamicSharedMemorySize, SMEMLN);
    const int SMEMPV = 65536 + 1024;             // softmax_pv: 2 x 32KB + smax/ssum
    cudaFuncSetAttribute(softmax_pv, cudaFuncAttributeMaxDynamicSharedMemorySize, SMEMPV);

    // prep
    split_kernel<<<4096, 256>>>(H_rna, pHrhi, pHrlo, (size_t)N * d);
    prep_small<<<512, 256>>>(H_drug, V, U, pHdhi, pHdlo, pHdThi, pVhi, pVlo, pUthi, pUtlo, pRM);

    // stages 1+2 fused: drug (blocks 0..31) -> DpT splits; rna -> A splits
    const int nblk1 = M / 64;                    // 32
    gemm_ln<<<nblk1 + N / 64, 512, SMEMLN>>>(
        pHdhi, pHdlo, pVhi, pVlo, g_drug, b_drug, pDpThi, pDpTlo, nblk1,
        pHrhi, pHrlo, pUthi, pUtlo, g_rna, b_rna, q, pAhi, pAlo);

    // stage 4: S = A @ Dp -> fp32 [N, M], fused per-row max (128x256 tiles)
    gemm_s<<<dim3(M / 256, N / 128), 512, SMEMS4>>>(pAhi, pAlo, pDpThi, pDpTlo, pS, K, M, pRM);

    // stages 5+6: out = softmax(S) @ H_drug
    softmax_pv<<<N / 128, 512, SMEMPV>>>(pS, pHdThi, pRM, (float*)d_out, M, d);
}

// round 17
// speedup vs baseline: 1.0771x; 1.0771x over previous
#include <cuda_runtime.h>
#include <cuda_fp16.h>
#include <cstdint>
#include <math.h>

// Fixed shapes (registry): N=65536, M=2048, d=256, K=512
#define NN 65536
#define MM 2048
#define DD 256
#define KK 512
#define LN_EPS 1e-5f

// ---------------- static scratch (no allocations allowed) ----------------
__device__ __align__(256) float  g_S   [(size_t)NN * MM];  // 512MB scores fp32
__device__ __align__(256) float  g_rowmax[NN];             // row maxima of S
__device__ __align__(256) __half g_Ahi [(size_t)NN * KK];
__device__ __align__(256) __half g_Alo [(size_t)NN * KK];
__device__ __align__(256) __half g_Hrhi[(size_t)NN * DD];
__device__ __align__(256) __half g_Hrlo[(size_t)NN * DD];
__device__ __align__(256) __half g_Hdhi[(size_t)MM * DD];
__device__ __align__(256) __half g_Hdlo[(size_t)MM * DD];
__device__ __align__(256) __half g_Vhi [(size_t)KK * DD];
__device__ __align__(256) __half g_Vlo [(size_t)KK * DD];
__device__ __align__(256) __half g_DpThi[(size_t)MM * KK];
__device__ __align__(256) __half g_DpTlo[(size_t)MM * KK];
__device__ __align__(256) __half g_HdThi[(size_t)DD * MM];
__device__ __align__(256) __half g_Uthi [(size_t)KK * DD];
__device__ __align__(256) __half g_Utlo [(size_t)KK * DD];

// ---------------- helpers ----------------
__device__ __forceinline__ uint32_t smem_u32(const void* p) {
    uint32_t a;
    asm("{ .reg .u64 t; cvta.to.shared.u64 t, %1; cvt.u32.u64 %0, t; }" : "=r"(a) : "l"(p));
    return a;
}
__device__ __forceinline__ void cp16(uint32_t dst, const void* src) {
    asm volatile("cp.async.cg.shared.global [%0], [%1], 16;" :: "r"(dst), "l"(src));
}
#define CP_COMMIT()  asm volatile("cp.async.commit_group;" ::: "memory")
#define CP_WAIT0()   asm volatile("cp.async.wait_group 0;"  ::: "memory")
#define CP_WAIT1()   asm volatile("cp.async.wait_group 1;"  ::: "memory")

#define LDSM4(r, addr) \
    asm volatile("ldmatrix.sync.aligned.m8n8.x4.shared.b16 {%0,%1,%2,%3}, [%4];" \
        : "=r"((r)[0]), "=r"((r)[1]), "=r"((r)[2]), "=r"((r)[3]) : "r"(addr))

#define MMA16816(c, a, b0, b1) \
    asm volatile("mma.sync.aligned.m16n8k16.row.col.f32.f16.f16.f32 " \
        "{%0,%1,%2,%3}, {%4,%5,%6,%7}, {%8,%9}, {%0,%1,%2,%3};" \
        : "+f"((c)[0]), "+f"((c)[1]), "+f"((c)[2]), "+f"((c)[3]) \
        : "r"((a)[0]), "r"((a)[1]), "r"((a)[2]), "r"((a)[3]), "r"(b0), "r"(b1))

__device__ __forceinline__ void split2h(float x, __half& h, __half& l) {
    h = __float2half(x);
    l = __float2half(x - __half2float(h));
}
__device__ __forceinline__ uint32_t pack2h(float a, float b) {
    __half2 h = __floats2half2_rn(a, b);
    return *(uint32_t*)&h;
}
__device__ __forceinline__ void atomicMaxFloat(float* addr, float val) {
    int* ia = (int*)addr;
    int old = *ia;
    while (__int_as_float(old) < val) {
        int assumed = old;
        old = atomicCAS(ia, assumed, __float_as_int(val));
        if (old == assumed) break;
    }
}

// ============ stage-4 HMMA GEMM (proven R15 config): 128x128, 3-stage, 2 CTA/SM ============
// fp16 x3 split; fused per-row max -> rowmax[]
__global__ void __launch_bounds__(256, 2)
gemm_hmma(const __half* __restrict__ Ahi, const __half* __restrict__ Alo,
          const __half* __restrict__ Bhi, const __half* __restrict__ Blo,
          float* __restrict__ C, int Ktot, int Ncols, float* __restrict__ rowmax)
{
    extern __shared__ char smem[];
    const int tid  = threadIdx.x;
    const int wid  = tid >> 5, lane = tid & 31;
    const int row0 = blockIdx.y * 128;
    const int col0 = blockIdx.x * 128;
    const int nch  = Ktot >> 5;

    const uint32_t sb = smem_u32(smem);

    const int wr = wid >> 1;
    const int wc = wid & 1;
    const int lm = lane >> 3;
    const int lr = lane & 7;

    float acc[2][8][4];
    #pragma unroll
    for (int i = 0; i < 2; i++)
        #pragma unroll
        for (int j = 0; j < 8; j++)
            #pragma unroll
            for (int k = 0; k < 4; k++) acc[i][j][k] = 0.f;

    auto load_chunk = [&](int ch, int stage) {
        const int kc0 = ch << 5;
        const uint32_t Ab = sb + (uint32_t)stage * 32768u;
        const uint32_t Bb = Ab + 16384u;
        #pragma unroll
        for (int g = tid; g < 2048; g += 256) {
            int mat = g >> 10;
            int r   = (g >> 3) & 127;
            int s   = g & 7;
            int split = s >> 2;
            int seg   = s & 3;
            const __half* srcb;
            int grow;
            if (mat == 0) { srcb = split ? Alo : Ahi; grow = row0 + r; }
            else          { srcb = split ? Blo : Bhi; grow = col0 + r; }
            const __half* src = srcb + (size_t)grow * Ktot + kc0 + seg * 8;
            uint32_t off = (uint32_t)(r * 128 + split * 64 + seg * 16);
            uint32_t dst = (mat ? Bb : Ab) + (off ^ ((off >> 3) & 0x70));
            cp16(dst, src);
        }
        CP_COMMIT();
    };

    auto compute = [&](int stage) {
        const uint32_t Ab = sb + (uint32_t)stage * 32768u;
        const uint32_t Bb = Ab + 16384u;
        #pragma unroll
        for (int ks = 0; ks < 2; ks++) {
            uint32_t ah[2][4], al[2][4];
            #pragma unroll
            for (int mt = 0; mt < 2; mt++) {
                int r = wr * 32 + mt * 16 + (lm & 1) * 8 + lr;
                int ch = ks * 32 + (lm >> 1) * 16;
                uint32_t rowa = Ab + (uint32_t)(r * 128);
                LDSM4(ah[mt], rowa + (uint32_t)( ch       ^ ((r & 7) << 4)));
                LDSM4(al[mt], rowa + (uint32_t)((ch + 64) ^ ((r & 7) << 4)));
            }
            uint32_t b[4][4];
            #pragma unroll
            for (int nt2 = 0; nt2 < 4; nt2++) {
                int r = wc * 64 + nt2 * 16 + (lm >> 1) * 8 + lr;
                int cb = ks * 32 + (lm & 1) * 16;
                LDSM4(b[nt2], Bb + (uint32_t)(r * 128) + (uint32_t)(cb ^ ((r & 7) << 4)));
            }
            #pragma unroll
            for (int mt = 0; mt < 2; mt++)
                #pragma unroll
                for (int nt = 0; nt < 8; nt++)
                    MMA16816(acc[mt][nt], ah[mt],
                             b[nt >> 1][(nt & 1) * 2], b[nt >> 1][(nt & 1) * 2 + 1]);
            #pragma unroll
            for (int mt = 0; mt < 2; mt++)
                #pragma unroll
                for (int nt = 0; nt < 8; nt++)
                    MMA16816(acc[mt][nt], al[mt],
                             b[nt >> 1][(nt & 1) * 2], b[nt >> 1][(nt & 1) * 2 + 1]);
            #pragma unroll
            for (int nt2 = 0; nt2 < 4; nt2++) {
                int r = wc * 64 + nt2 * 16 + (lm >> 1) * 8 + lr;
                int cb = 64 + ks * 32 + (lm & 1) * 16;
                LDSM4(b[nt2], Bb + (uint32_t)(r * 128) + (uint32_t)(cb ^ ((r & 7) << 4)));
            }
            #pragma unroll
            for (int mt = 0; mt < 2; mt++)
                #pragma unroll
                for (int nt = 0; nt < 8; nt++)
                    MMA16816(acc[mt][nt], ah[mt],
                             b[nt >> 1][(nt & 1) * 2], b[nt >> 1][(nt & 1) * 2 + 1]);
        }
    };

    load_chunk(0, 0);
    load_chunk(1, 1);
    for (int i = 0; i < nch; i++) {
        if (i + 1 < nch) CP_WAIT1(); else CP_WAIT0();
        __syncthreads();
        if (i + 2 < nch) {
            int st = i + 2; st -= (st / 3) * 3;
            load_chunk(i + 2, st);
        }
        int cs = i; cs -= (cs / 3) * 3;
        compute(cs);
    }

    #pragma unroll
    for (int mt = 0; mt < 2; mt++) {
        float rmax0 = -INFINITY, rmax1 = -INFINITY;
        #pragma unroll
        for (int nt = 0; nt < 8; nt++) {
            int r = row0 + wr * 32 + mt * 16 + (lane >> 2);
            int c = col0 + wc * 64 + nt * 8 + (lane & 3) * 2;
            float2 v0 = make_float2(acc[mt][nt][0], acc[mt][nt][1]);
            float2 v1 = make_float2(acc[mt][nt][2], acc[mt][nt][3]);
            rmax0 = fmaxf(rmax0, fmaxf(v0.x, v0.y));
            rmax1 = fmaxf(rmax1, fmaxf(v1.x, v1.y));
            *(float2*)&C[(size_t)r * Ncols + c]       = v0;
            *(float2*)&C[(size_t)(r + 8) * Ncols + c] = v1;
        }
        rmax0 = fmaxf(rmax0, __shfl_xor_sync(0xffffffffu, rmax0, 1));
        rmax0 = fmaxf(rmax0, __shfl_xor_sync(0xffffffffu, rmax0, 2));
        rmax1 = fmaxf(rmax1, __shfl_xor_sync(0xffffffffu, rmax1, 1));
        rmax1 = fmaxf(rmax1, __shfl_xor_sync(0xffffffffu, rmax1, 2));
        if ((lane & 3) == 0) {
            int r = row0 + wr * 32 + mt * 16 + (lane >> 2);
            atomicMaxFloat(&rowmax[r],     rmax0);
            atomicMaxFloat(&rowmax[r + 8], rmax1);
        }
    }
}

// ============ fused GEMM + tanh + LayerNorm (+ optional *q) + fp16 split ============
// (unchanged from R15 — proven)
__global__ void __launch_bounds__(512, 1)
gemm_ln(const __half* __restrict__ A1hi, const __half* __restrict__ A1lo,
        const __half* __restrict__ B1hi, const __half* __restrict__ B1lo,
        const float* __restrict__ g1, const float* __restrict__ b1,
        __half* __restrict__ O1hi, __half* __restrict__ O1lo, int nblk1,
        const __half* __restrict__ A2hi, const __half* __restrict__ A2lo,
        const __half* __restrict__ B2hi, const __half* __restrict__ B2lo,
        const float* __restrict__ g2, const float* __restrict__ b2,
        const float* __restrict__ q2,
        __half* __restrict__ O2hi, __half* __restrict__ O2lo)
{
    extern __shared__ char smem[];
    float* lnsum  = (float*)(smem + 3 * 73728);
    float* lnsum2 = lnsum + 64;
    const uint32_t sb = smem_u32(smem);

    const bool job2 = (int)blockIdx.x >= nblk1;
    const __half* Ahi = job2 ? A2hi : A1hi;
    const __half* Alo = job2 ? A2lo : A1lo;
    const __half* Bhi = job2 ? B2hi : B1hi;
    const __half* Blo = job2 ? B2lo : B1lo;
    const float*  gp  = job2 ? g2 : g1;
    const float*  bp  = job2 ? b2 : b1;
    __half* Ohi = job2 ? O2hi : O1hi;
    __half* Olo = job2 ? O2lo : O1lo;
    const int row0 = (job2 ? ((int)blockIdx.x - nblk1) : (int)blockIdx.x) * 64;

    const int tid  = threadIdx.x;
    const int wid  = tid >> 5, lane = tid & 31;
    const int wr = wid >> 2, wc = wid & 3;
    const int lm = lane >> 3, lr = lane & 7;

    if (tid < 64) { lnsum[tid] = 0.f; lnsum2[tid] = 0.f; }

    float acc[16][4];
    #pragma unroll
    for (int i = 0; i < 16; i++)
        #pragma unroll
        for (int j = 0; j < 4; j++) acc[i][j] = 0.f;

    auto load_chunk = [&](int ch, int stage) {
        const int kc0 = ch << 5;
        const uint32_t Ab = sb + (uint32_t)stage * 73728u;
        const uint32_t Bb = Ab + 8192u;
        {
            int r = tid >> 3, s = tid & 7;
            int split = s >> 2, seg = s & 3;
            const __half* src = (split ? Alo : Ahi) + (size_t)(row0 + r) * 256 + kc0 + seg * 8;
            uint32_t off = (uint32_t)(r * 128 + split * 64 + seg * 16);
            cp16(Ab + (off ^ ((off >> 3) & 0x70)), src);
        }
        #pragma unroll
        for (int g = tid; g < 4096; g += 512) {
            int r = g >> 3, s = g & 7;
            int split = s >> 2, seg = s & 3;
            const __half* src = (split ? Blo : Bhi) + (size_t)r * 256 + kc0 + seg * 8;
            uint32_t off = (uint32_t)(r * 128 + split * 64 + seg * 16);
            cp16(Bb + (off ^ ((off >> 3) & 0x70)), src);
        }
        CP_COMMIT();
    };

    auto compute = [&](int stage) {
        const uint32_t Ab = sb + (uint32_t)stage * 73728u;
        const uint32_t Bb = Ab + 8192u;
        #pragma unroll
        for (int ks = 0; ks < 2; ks++) {
            uint32_t ah[4], al[4];
            {
                int r = wr * 16 + (lm & 1) * 8 + lr;
                int ch = ks * 32 + (lm >> 1) * 16;
                uint32_t rowa = Ab + (uint32_t)(r * 128);
                LDSM4(ah, rowa + (uint32_t)( ch       ^ ((r & 7) << 4)));
                LDSM4(al, rowa + (uint32_t)((ch + 64) ^ ((r & 7) << 4)));
            }
            #pragma unroll
            for (int half = 0; half < 2; half++) {
                uint32_t b[4][4];
                #pragma unroll
                for (int nt2 = 0; nt2 < 4; nt2++) {
                    int gi = half * 4 + nt2;
                    int r  = wc * 128 + gi * 16 + (lm >> 1) * 8 + lr;
                    int cb = ks * 32 + (lm & 1) * 16;
                    LDSM4(b[nt2], Bb + (uint32_t)(r * 128) + (uint32_t)(cb ^ ((r & 7) << 4)));
                }
                #pragma unroll
                for (int nt2 = 0; nt2 < 4; nt2++) {
                    int ai = (half * 4 + nt2) * 2;
                    MMA16816(acc[ai],     ah, b[nt2][0], b[nt2][1]);
                    MMA16816(acc[ai + 1], ah, b[nt2][2], b[nt2][3]);
                    MMA16816(acc[ai],     al, b[nt2][0], b[nt2][1]);
                    MMA16816(acc[ai + 1], al, b[nt2][2], b[nt2][3]);
                }
                #pragma unroll
                for (int nt2 = 0; nt2 < 4; nt2++) {
                    int gi = half * 4 + nt2;
                    int r  = wc * 128 + gi * 16 + (lm >> 1) * 8 + lr;
                    int cb = 64 + ks * 32 + (lm & 1) * 16;
                    LDSM4(b[nt2], Bb + (uint32_t)(r * 128) + (uint32_t)(cb ^ ((r & 7) << 4)));
                }
                #pragma unroll
                for (int nt2 = 0; nt2 < 4; nt2++) {
                    int ai = (half * 4 + nt2) * 2;
                    MMA16816(acc[ai],     ah, b[nt2][0], b[nt2][1]);
                    MMA16816(acc[ai + 1], ah, b[nt2][2], b[nt2][3]);
                }
            }
        }
    };

    load_chunk(0, 0);
    load_chunk(1, 1);
    for (int i = 0; i < 8; i++) {
        if (i + 1 < 8) CP_WAIT1(); else CP_WAIT0();
        __syncthreads();
        if (i + 2 < 8) {
            int st = i + 2; st -= (st / 3) * 3;
            load_chunk(i + 2, st);
        }
        int cs = i; cs -= (cs / 3) * 3;
        compute(cs);
    }

    const int r0l = wr * 16 + (lane >> 2);
    float s0 = 0.f, s20 = 0.f, s1 = 0.f, s21 = 0.f;
    #pragma unroll
    for (int ai = 0; ai < 16; ai++) {
        float v0 = tanhf(acc[ai][0]), v1 = tanhf(acc[ai][1]);
        float v2 = tanhf(acc[ai][2]), v3 = tanhf(acc[ai][3]);
        acc[ai][0] = v0; acc[ai][1] = v1; acc[ai][2] = v2; acc[ai][3] = v3;
        s0 += v0 + v1; s20 += v0 * v0 + v1 * v1;
        s1 += v2 + v3; s21 += v2 * v2 + v3 * v3;
    }
    s0  += __shfl_xor_sync(0xffffffffu, s0, 1);  s0  += __shfl_xor_sync(0xffffffffu, s0, 2);
    s20 += __shfl_xor_sync(0xffffffffu, s20, 1); s20 += __shfl_xor_sync(0xffffffffu, s20, 2);
    s1  += __shfl_xor_sync(0xffffffffu, s1, 1);  s1  += __shfl_xor_sync(0xffffffffu, s1, 2);
    s21 += __shfl_xor_sync(0xffffffffu, s21, 1); s21 += __shfl_xor_sync(0xffffffffu, s21, 2);
    if ((lane & 3) == 0) {
        atomicAdd(&lnsum [r0l],     s0);
        atomicAdd(&lnsum2[r0l],     s20);
        atomicAdd(&lnsum [r0l + 8], s1);
        atomicAdd(&lnsum2[r0l + 8], s21);
    }
    __syncthreads();

    const float mu0   = lnsum[r0l] * (1.f / 512.f);
    const float rstd0 = rsqrtf(lnsum2[r0l] * (1.f / 512.f) - mu0 * mu0 + LN_EPS);
    const float mu1   = lnsum[r0l + 8] * (1.f / 512.f);
    const float rstd1 = rsqrtf(lnsum2[r0l + 8] * (1.f / 512.f) - mu1 * mu1 + LN_EPS);
    const int grow = row0 + r0l;

    #pragma unroll
    for (int ai = 0; ai < 16; ai++) {
        int c = wc * 128 + (ai >> 1) * 16 + (ai & 1) * 8 + (lane & 3) * 2;
        float2 gv = *(const float2*)(gp + c);
        float2 bv = *(const float2*)(bp + c);
        float y0 = (acc[ai][0] - mu0) * rstd0 * gv.x + bv.x;
        float y1 = (acc[ai][1] - mu0) * rstd0 * gv.y + bv.y;
        float y2 = (acc[ai][2] - mu1) * rstd1 * gv.x + bv.x;
        float y3 = (acc[ai][3] - mu1) * rstd1 * gv.y + bv.y;
        if (job2) {
            float2 qv = *(const float2*)(q2 + c);
            y0 *= qv.x; y1 *= qv.y; y2 *= qv.x; y3 *= qv.y;
        }
        __half h0, l0, h1, l1, h2, l2, h3, l3;
        split2h(y0, h0, l0); split2h(y1, h1, l1);
        split2h(y2, h2, l2); split2h(y3, h3, l3);
        *(__half2*)&Ohi[(size_t)grow * 512 + c]       = __halves2half2(h0, h1);
        *(__half2*)&Olo[(size_t)grow * 512 + c]       = __halves2half2(l0, l1);
        *(__half2*)&Ohi[(size_t)(grow + 8) * 512 + c] = __halves2half2(h2, h3);
        *(__half2*)&Olo[(size_t)(grow + 8) * 512 + c] = __halves2half2(l2, l3);
    }
}

// ============ fused softmax + O = softmax(S) @ Hd, with dead-chunk skipping ============
// Softmax is peaked (std(S)~22): entries below rowmax-18 contribute < 2048*e^-18 ~ 3e-5
// relative. Per 32-col chunk, a block-wide vote (syncthreads_or, doubling as the barrier)
// skips exp/pack/LDSM/MMA for chunks with no live element.
__global__ void __launch_bounds__(512, 1)
softmax_pv(const float* __restrict__ S, const __half* __restrict__ HdThi,
           const float* __restrict__ rowmax, float* __restrict__ O, int M, int d)
{
    extern __shared__ char smem[];
    float* smax = (float*)(smem + 65536);
    float* ssum = smax + 128;
    const uint32_t sb = smem_u32(smem);
    const int tid  = threadIdx.x;
    const int wid  = tid >> 5, lane = tid & 31;
    const int wr   = wid >> 1, wc = wid & 1;
    const int lm   = lane >> 3, lr = lane & 7;
    const int row0 = blockIdx.x * 128;

    if (tid < 128) {
        smax[tid] = rowmax[row0 + tid];
        ssum[tid] = 0.f;
    }
    __syncthreads();

    const int nch  = M >> 5;
    const int r0l  = wr * 16 + (lane >> 2);
    const float mx0 = smax[r0l];
    const float mx1 = smax[r0l + 8];
    const float* Sr0 = S + (size_t)(row0 + r0l) * M + (lane & 3) * 2;
    const float* Sr1 = S + (size_t)(row0 + r0l + 8) * M + (lane & 3) * 2;

    float acc[16][4];
    #pragma unroll
    for (int i = 0; i < 16; i++)
        #pragma unroll
        for (int j = 0; j < 4; j++) acc[i][j] = 0.f;
    float psum0 = 0.f, psum1 = 0.f;

    auto loadB = [&](int ch, int buf) {
        const int m0 = ch << 5;
        const uint32_t Bb = sb + (uint32_t)buf * 32768u;
        #pragma unroll
        for (int g = tid; g < 1024; g += 512) {
            int r = g >> 2, seg = g & 3;
            const __half* src = HdThi + (size_t)r * M + m0 + seg * 8;
            uint32_t off = (uint32_t)(r * 128 + seg * 16);
            cp16(Bb + (off ^ ((off >> 3) & 0x70)), src);
        }
        CP_COMMIT();
    };
    auto loadS = [&](int ch, float2* sp) {
        const int c0 = ch << 5;
        sp[0] = *(const float2*)(Sr0 + c0);
        sp[1] = *(const float2*)(Sr0 + c0 + 8);
        sp[2] = *(const float2*)(Sr0 + c0 + 16);
        sp[3] = *(const float2*)(Sr0 + c0 + 24);
        sp[4] = *(const float2*)(Sr1 + c0);
        sp[5] = *(const float2*)(Sr1 + c0 + 8);
        sp[6] = *(const float2*)(Sr1 + c0 + 16);
        sp[7] = *(const float2*)(Sr1 + c0 + 24);
    };

    float2 spc[8];
    loadB(0, 0);
    loadS(0, spc);

    const float THR = -18.f;

    for (int c = 0; c < nch; c++) {
        float2 spn[8];
        if (c + 1 < nch) {
            loadB(c + 1, (c + 1) & 1);
            loadS(c + 1, spn);
            CP_WAIT1();
        } else {
            CP_WAIT0();
        }

        // liveness vote: any element in this chunk above its row's (max + THR)?
        float m0v = fmaxf(fmaxf(spc[0].x, spc[0].y), fmaxf(spc[1].x, spc[1].y));
        m0v = fmaxf(m0v, fmaxf(fmaxf(spc[2].x, spc[2].y), fmaxf(spc[3].x, spc[3].y)));
        float m1v = fmaxf(fmaxf(spc[4].x, spc[4].y), fmaxf(spc[5].x, spc[5].y));
        m1v = fmaxf(m1v, fmaxf(fmaxf(spc[6].x, spc[6].y), fmaxf(spc[7].x, spc[7].y)));
        int live = (m0v - mx0 >= THR) || (m1v - mx1 >= THR);
        int any = __syncthreads_or(live);      // doubles as the post-CP_WAIT barrier

        if (any) {
            const uint32_t Bb = sb + (uint32_t)(c & 1) * 32768u;
            #pragma unroll
            for (int ks = 0; ks < 2; ks++) {
                float e00 = __expf(spc[2*ks    ].x - mx0), e01 = __expf(spc[2*ks    ].y - mx0);
                float e02 = __expf(spc[2*ks + 1].x - mx0), e03 = __expf(spc[2*ks + 1].y - mx0);
                float e10 = __expf(spc[4 + 2*ks    ].x - mx1), e11 = __expf(spc[4 + 2*ks    ].y - mx1);
                float e12 = __expf(spc[4 + 2*ks + 1].x - mx1), e13 = __expf(spc[4 + 2*ks + 1].y - mx1);
                psum0 += e00 + e01 + e02 + e03;
                psum1 += e10 + e11 + e12 + e13;
                uint32_t ah[4];
                ah[0] = pack2h(e00, e01); ah[1] = pack2h(e10, e11);
                ah[2] = pack2h(e02, e03); ah[3] = pack2h(e12, e13);
                #pragma unroll
                for (int nt2 = 0; nt2 < 8; nt2++) {
                    int r  = wc * 128 + nt2 * 16 + (lm >> 1) * 8 + lr;
                    int cb = ks * 32 + (lm & 1) * 16;
                    uint32_t b[4];
                    LDSM4(b, Bb + (uint32_t)(r * 128) + (uint32_t)(cb ^ ((r & 7) << 4)));
                    MMA16816(acc[nt2 * 2    ], ah, b[0], b[1]);
                    MMA16816(acc[nt2 * 2 + 1], ah, b[2], b[3]);
                }
            }
        }
        #pragma unroll
        for (int i = 0; i < 8; i++) spc[i] = spn[i];
        __syncthreads();
    }

    psum0 += __shfl_xor_sync(0xffffffffu, psum0, 1);
    psum0 += __shfl_xor_sync(0xffffffffu, psum0, 2);
    psum1 += __shfl_xor_sync(0xffffffffu, psum1, 1);
    psum1 += __shfl_xor_sync(0xffffffffu, psum1, 2);
    if ((lane & 3) == 0 && wc == 0) {
        atomicAdd(&ssum[r0l],     psum0);
        atomicAdd(&ssum[r0l + 8], psum1);
    }
    __syncthreads();
    const float inv0 = 1.f / ssum[r0l];
    const float inv1 = 1.f / ssum[r0l + 8];

    #pragma unroll
    for (int nt2 = 0; nt2 < 8; nt2++) {
        #pragma unroll
        for (int j = 0; j < 2; j++) {
            int col = wc * 128 + nt2 * 16 + j * 8 + (lane & 3) * 2;
            float* a4 = acc[nt2 * 2 + j];
            *(float2*)&O[(size_t)(row0 + r0l)     * d + col] =
                make_float2(a4[0] * inv0, a4[1] * inv0);
            *(float2*)&O[(size_t)(row0 + r0l + 8) * d + col] =
                make_float2(a4[2] * inv1, a4[3] * inv1);
        }
    }
}

// ---------------- prep kernels ----------------
__global__ void split_kernel(const float* __restrict__ in,
                             __half* __restrict__ hi, __half* __restrict__ lo, size_t n)
{
    for (size_t i = (size_t)blockIdx.x * blockDim.x + threadIdx.x; i < n;
         i += (size_t)gridDim.x * blockDim.x) {
        __half h, l; split2h(in[i], h, l);
        hi[i] = h; lo[i] = l;
    }
}

__global__ void prep_small(const float* __restrict__ Hd, const float* __restrict__ V,
                           const float* __restrict__ U,
                           __half* __restrict__ Hdhi, __half* __restrict__ Hdlo,
                           __half* __restrict__ HdThi,
                           __half* __restrict__ Vhi, __half* __restrict__ Vlo,
                           __half* __restrict__ Uthi, __half* __restrict__ Utlo,
                           float* __restrict__ rm)
{
    const int i0 = blockIdx.x * blockDim.x + threadIdx.x;
    const int stride = gridDim.x * blockDim.x;
    for (int t = i0; t < MM * DD; t += stride) {
        __half h, l; split2h(Hd[t], h, l);
        Hdhi[t] = h; Hdlo[t] = l;
        int m = t >> 8, dd = t & 255;
        HdThi[(size_t)dd * MM + m] = h;
    }
    for (int t = i0; t < KK * DD; t += stride) {
        __half h, l; split2h(V[t], h, l);
        Vhi[t] = h; Vlo[t] = l;
    }
    for (int t = i0; t < DD * KK; t += stride) {
        int r = t >> 9, c = t & 511;
        __half h, l; split2h(U[t], h, l);
        Uthi[(size_t)c * DD + r] = h;
        Utlo[(size_t)c * DD + r] = l;
    }
    for (int t = i0; t < NN; t += stride) rm[t] = -INFINITY;
}

// ---------------- launch ----------------
extern "C" void kernel_launch(void* const* d_in, const int* in_sizes, int n_in,
                              void* d_out, int out_size)
{
    const float* H_rna  = (const float*)d_in[0];
    const float* H_drug = (const float*)d_in[1];
    const float* U      = (const float*)d_in[2];
    const float* V      = (const float*)d_in[3];
    const float* q      = (const float*)d_in[4];
    const float* g_rna  = (const float*)d_in[5];
    const float* b_rna  = (const float*)d_in[6];
    const float* g_drug = (const float*)d_in[7];
    const float* b_drug = (const float*)d_in[8];

    const int K = in_sizes[4];             // 512
    const int d = in_sizes[2] / K;         // 256
    const int N = in_sizes[0] / d;         // 65536
    const int M = in_sizes[1] / d;         // 2048

    float *pS, *pRM;
    __half *pAhi, *pAlo, *pHrhi, *pHrlo, *pHdhi, *pHdlo, *pVhi, *pVlo;
    __half *pDpThi, *pDpTlo, *pHdThi, *pUthi, *pUtlo;
    cudaGetSymbolAddress((void**)&pS,     g_S);
    cudaGetSymbolAddress((void**)&pRM,    g_rowmax);
    cudaGetSymbolAddress((void**)&pAhi,   g_Ahi);
    cudaGetSymbolAddress((void**)&pAlo,   g_Alo);
    cudaGetSymbolAddress((void**)&pHrhi,  g_Hrhi);
    cudaGetSymbolAddress((void**)&pHrlo,  g_Hrlo);
    cudaGetSymbolAddress((void**)&pHdhi,  g_Hdhi);
    cudaGetSymbolAddress((void**)&pHdlo,  g_Hdlo);
    cudaGetSymbolAddress((void**)&pVhi,   g_Vhi);
    cudaGetSymbolAddress((void**)&pVlo,   g_Vlo);
    cudaGetSymbolAddress((void**)&pDpThi, g_DpThi);
    cudaGetSymbolAddress((void**)&pDpTlo, g_DpTlo);
    cudaGetSymbolAddress((void**)&pHdThi, g_HdThi);
    cudaGetSymbolAddress((void**)&pUthi,  g_Uthi);
    cudaGetSymbolAddress((void**)&pUtlo,  g_Utlo);

    const int SMEMSZ = 98304;                    // gemm_hmma: 3 x 32KB
    cudaFuncSetAttribute(gemm_hmma, cudaFuncAttributeMaxDynamicSharedMemorySize, SMEMSZ);
    const int SMEMLN = 3 * 73728 + 512;          // gemm_ln: 3 x 72KB + lnsum
    cudaFuncSetAttribute(gemm_ln, cudaFuncAttributeMaxDynamicSharedMemorySize, SMEMLN);
    const int SMEMPV = 65536 + 1024;             // softmax_pv: 2 x 32KB + smax/ssum
    cudaFuncSetAttribute(softmax_pv, cudaFuncAttributeMaxDynamicSharedMemorySize, SMEMPV);

    // prep
    split_kernel<<<4096, 256>>>(H_rna, pHrhi, pHrlo, (size_t)N * d);
    prep_small<<<512, 256>>>(H_drug, V, U, pHdhi, pHdlo, pHdThi, pVhi, pVlo, pUthi, pUtlo, pRM);

    // stages 1+2 fused: drug (blocks 0..31) -> DpT splits; rna -> A splits
    const int nblk1 = M / 64;                    // 32
    gemm_ln<<<nblk1 + N / 64, 512, SMEMLN>>>(
        pHdhi, pHdlo, pVhi, pVlo, g_drug, b_drug, pDpThi, pDpTlo, nblk1,
        pHrhi, pHrlo, pUthi, pUtlo, g_rna, b_rna, q, pAhi, pAlo);

    // stage 4: S = A @ Dp -> fp32 [N, M], fused per-row max (proven 128x128, 2 CTA/SM)
    gemm_hmma<<<dim3(M / 128, N / 128), 256, SMEMSZ>>>(pAhi, pAlo, pDpThi, pDpTlo, pS, K, M, pRM);

    // stages 5+6: out = softmax(S) @ H_drug  (dead-chunk skipping)
    softmax_pv<<<N / 128, 512, SMEMPV>>>(pS, pHdThi, pRM, (float*)d_out, M, d);
}